// round 17
// baseline (speedup 1.0000x reference)
#include <cuda_runtime.h>
#include <cuda_fp16.h>
#include <cuda_bf16.h>
#include <cstdint>

#define NB   16384
#define NE   8
#define DIN  900
#define DM   512
#define DSEL 128
#define EPSF 1e-9f

#define KP     928            // 58 * 16, zero-padded K
#define NSUP   29             // super k-steps of K=32
#define NSTG   4              // super-stage pipeline depth
#define SSTAGE 24576          // bytes per super-stage (2 subs x 3 arrays x 128 x 32B)
#define SUB    12288          // per 16-K sub-block: a1 4KB | a2 4KB | b 4KB
#define A1OFF  0
#define A2OFF  4096
#define BOFF   8192
#define DYNSM  (NSTG * SSTAGE) // 98304

#define OUT_GUIDE (NB * DM)
#define OUT_SEL   (NB * DM + 1)

// prep grid layout (1024-thread blocks)
#define PREP_PHA   512                     // phaseA blocks
#define PREP_SX    1856                    // split_x blocks (NB*116/1024)
#define PREP_SW    3712                    // split_w blocks (29*16*8)
#define PREP_GRID  (PREP_PHA + PREP_SX + PREP_SW)

// post grid layout (256-thread blocks)
#define POST_CMB   8192                    // combine blocks (NB*DM/4/256)
#define POST_SEL   2048                    // selemb blocks (NB/8)
#define POST_GRID  (POST_CMB + POST_SEL + 1)

__device__ float g_scratch[(size_t)2 * NB * DM];     // gated per-(token,slot) outputs
__device__ int   g_bucket[NE * NB];
__device__ int   g_count[NE];                        // zero-init at load; combine resets
__device__ float g_gate[2 * NB];
__device__ float g_iw[NB * NE];                      // inactive-mixture weights
__device__ float g_partial[512];
__device__ __half g_Xh1[(size_t)NB * KP];            // X fp16 hi limb
__device__ __half g_Xh2[(size_t)NB * KP];            // X fp16 lo limb
__device__ __half g_Wh[(size_t)NE * DM * KP];        // W transposed [e][n][k], fp16

// ---------------------------------------------------------------------------
__device__ __forceinline__ uint32_t smem_u32(const void* p) {
    return (uint32_t)__cvta_generic_to_shared(p);
}
__device__ __forceinline__ void cp16(uint32_t s, const void* g) {
    asm volatile("cp.async.cg.shared.global [%0], [%1], 16;" :: "r"(s), "l"(g));
}
// .noinc: arrive against the initialized expect-count (default variant
// increments pending count first -> net zero -> deadlock; R15 lesson).
__device__ __forceinline__ void cp_mbar_arrive_noinc(uint32_t mbar) {
    asm volatile("cp.async.mbarrier.arrive.noinc.shared.b64 [%0];"
                 :: "r"(mbar) : "memory");
}
__device__ __forceinline__ void mbar_init(uint32_t mbar, uint32_t cnt) {
    asm volatile("mbarrier.init.shared.b64 [%0], %1;" :: "r"(mbar), "r"(cnt) : "memory");
}
__device__ __forceinline__ void mbar_arrive(uint32_t mbar) {
    asm volatile("mbarrier.arrive.shared.b64 _, [%0];" :: "r"(mbar) : "memory");
}
__device__ __forceinline__ void mbar_wait(uint32_t mbar, uint32_t parity) {
    asm volatile(
        "{\n\t.reg .pred P;\n\t"
        "WL_%=:\n\t"
        "mbarrier.try_wait.parity.shared.b64 P, [%0], %1, 0x989680;\n\t"
        "@P bra.uni WD_%=;\n\t"
        "bra.uni WL_%=;\n\t"
        "WD_%=:\n\t}"
        :: "r"(mbar), "r"(parity) : "memory");
}
__device__ __forceinline__ void ldm_x4(uint32_t* r, uint32_t a) {
    asm volatile("ldmatrix.sync.aligned.m8n8.x4.shared.b16 {%0,%1,%2,%3}, [%4];"
                 : "=r"(r[0]), "=r"(r[1]), "=r"(r[2]), "=r"(r[3]) : "r"(a));
}
#define MMA_F16(acc, a, b) \
    asm volatile("mma.sync.aligned.m16n8k16.row.col.f32.f16.f16.f32 " \
        "{%0,%1,%2,%3}, {%4,%5,%6,%7}, {%8,%9}, {%0,%1,%2,%3};" \
        : "+f"((acc)[0]), "+f"((acc)[1]), "+f"((acc)[2]), "+f"((acc)[3]) \
        : "r"((a)[0]), "r"((a)[1]), "r"((a)[2]), "r"((a)[3]), \
          "r"((b)[0]), "r"((b)[1]))

// swizzled offset for (row, chunk16) in a Nx32B array: kills LDSM conflicts
__device__ __forceinline__ uint32_t swz(int row, int chunk) {
    return (uint32_t)(row * 32 + (chunk ^ ((row >> 2) & 1)) * 16);
}

// ---------------------------------------------------------------------------
// PREP: one heterogeneous grid fusing phaseA + split_x + split_w (independent
// roles co-scheduled across SMs; outputs disjoint; gemm depends on all).
__global__ void __launch_bounds__(1024) prep_kernel(
    const float* __restrict__ logits,
    const int*   __restrict__ masks,
    const float* __restrict__ X,
    const float* __restrict__ W)
{
    int bx = blockIdx.x;
    int tid = threadIdx.x;

    if (bx < PREP_PHA) {
        // ---- phaseA: softmax, gates, top-2, bucketing, guide partials
        __shared__ int   lcount[NE];
        __shared__ int   lbase[NE];
        __shared__ int   staging[NE][32];
        __shared__ float warpS[32];

        int warp = tid >> 5;
        int lane = tid & 31;
        if (tid < NE) lcount[tid] = 0;
        __syncthreads();

        int b = bx * 32 + warp;

        float raw[NE];
        float mx = -1e30f;
#pragma unroll
        for (int e = 0; e < NE; e++) { raw[e] = logits[b * NE + e]; mx = fmaxf(mx, raw[e]); }
        float sum = 0.f;
#pragma unroll
        for (int e = 0; e < NE; e++) { raw[e] = expf(raw[e] - mx); sum += raw[e]; }
        float inv = 1.f / sum;
        int m[NE];
#pragma unroll
        for (int e = 0; e < NE; e++) { raw[e] *= inv; m[e] = masks[b * NE + e]; }

        float w[NE]; float isum = 0.f;
#pragma unroll
        for (int e = 0; e < NE; e++) { w[e] = (m[e] == 1) ? 0.f : raw[e]; isum += w[e]; }
        float winv = 1.f / (isum + EPSF);

        float a[NE]; float srow = 0.f;
#pragma unroll
        for (int e = 0; e < NE; e++) {
            w[e] *= winv;
            a[e] = (m[e] == 1) ? raw[e] : 0.f;
            srow += a[e];
        }

        float v1 = -1.f, v2 = -1.f; int e1 = 0, e2 = 0;
#pragma unroll
        for (int e = 0; e < NE; e++) {
            if (a[e] > v1) { v2 = v1; e2 = e1; v1 = a[e]; e1 = e; }
            else if (a[e] > v2) { v2 = a[e]; e2 = e; }
        }
        float gs = 1.f / (v1 + v2 + EPSF);
        float g1 = v1 * gs, g2 = v2 * gs;

        if (lane == 0) {
#pragma unroll
            for (int e = 0; e < NE; e++) g_iw[b * NE + e] = w[e];
            g_gate[2 * b]     = g1;
            g_gate[2 * b + 1] = g2;
            if (g1 > 0.f) { int p = atomicAdd(&lcount[e1], 1); staging[e1][p] = 2 * b; }
            if (g2 > 0.f) { int p = atomicAdd(&lcount[e2], 1); staging[e2][p] = 2 * b + 1; }
            warpS[warp] = srow;
        }
        __syncthreads();
        if (tid < NE) lbase[tid] = atomicAdd(&g_count[tid], lcount[tid]);
        if (tid == 0) {
            float s = 0.f;
            for (int i = 0; i < 32; i++) s += warpS[i];
            g_partial[bx] = s;
        }
        __syncthreads();
#pragma unroll
        for (int e = 0; e < NE; e++) {
            for (int i = tid; i < lcount[e]; i += blockDim.x)
                g_bucket[e * NB + lbase[e] + i] = staging[e][i];
        }
    } else if (bx < PREP_PHA + PREP_SX) {
        // ---- split_x: fp16 hi/lo limbs, 8 elems/thread
        int idx = (bx - PREP_PHA) * 1024 + tid;
        int b = idx / 116, j = idx % 116;      // 116 * 8 = 928 = KP
        int k0 = j * 8;
        float v[8];
        if (k0 + 8 <= DIN) {
            float4 u0 = *(const float4*)(X + (size_t)b * DIN + k0);
            float4 u1 = *(const float4*)(X + (size_t)b * DIN + k0 + 4);
            v[0] = u0.x; v[1] = u0.y; v[2] = u0.z; v[3] = u0.w;
            v[4] = u1.x; v[5] = u1.y; v[6] = u1.z; v[7] = u1.w;
        } else {
#pragma unroll
            for (int q = 0; q < 8; q++)
                v[q] = (k0 + q < DIN) ? X[(size_t)b * DIN + k0 + q] : 0.f;
        }
        __half2 h1[4], h2[4];
#pragma unroll
        for (int q = 0; q < 4; q++) {
            __half a = __float2half(v[2 * q]), c = __float2half(v[2 * q + 1]);
            h1[q] = __halves2half2(a, c);
            h2[q] = __halves2half2(__float2half(v[2 * q] - __half2float(a)),
                                   __float2half(v[2 * q + 1] - __half2float(c)));
        }
        *(float4*)(g_Xh1 + (size_t)b * KP + k0) = *(float4*)h1;
        *(float4*)(g_Xh2 + (size_t)b * KP + k0) = *(float4*)h2;
    } else {
        // ---- split_w: transpose W[e][k][n] -> g_Wh[e][n][kpad], 32x32 tiles,
        // one element per thread (1024 threads = full tile)
        __shared__ float tile[32][33];
        int bw = bx - PREP_PHA - PREP_SX;
        int kt = bw % 29;
        int nt = (bw / 29) & 15;
        int e  = bw / (29 * 16);
        int tx = tid & 31, ty = tid >> 5;

        int k = kt * 32 + ty, n = nt * 32 + tx;
        tile[ty][tx] = (k < DIN) ? W[((size_t)e * DIN + k) * DM + n] : 0.f;
        __syncthreads();
        int nw = nt * 32 + ty, kw = kt * 32 + tx;
        g_Wh[((size_t)e * DM + nw) * KP + kw] = __float2half(tile[tx][ty]);
    }
}

// ---------------------------------------------------------------------------
// Tensor-core grouped GEMM (R16, proven): mma.sync fp16, 2-pass X-limb split.
// CTA tile 128x128, 8 warps (2m x 4n, 64x32 warp tiles), 2 CTAs/SM.
// Barrier-free mbarrier pipeline — full[s]/empty[s] per stage, warps free-run.
extern __shared__ char sm_dyn[];

__global__ void __launch_bounds__(256, 2) gemm_kernel(
    const float* __restrict__ bias)
{
    int e   = blockIdx.z;
    int cnt = g_count[e];
    int rt0 = blockIdx.x * 128;
    if (rt0 >= cnt) return;
    int rows = cnt - rt0; if (rows > 128) rows = 128;
    int n0 = blockIdx.y * 128;

    __shared__ int   sEntry[128];
    __shared__ float sGate[128];
    __shared__ float sBias[128];
    __shared__ __align__(8) unsigned long long s_full[NSTG], s_empty[NSTG];

    int t = threadIdx.x;
    int wid = t >> 5, lane = t & 31;
    int wm = wid & 1, wn = wid >> 1;       // 2 x 4 warp grid

    if (t < 128) {
        int entry = 0; float g = 0.f;
        if (t < rows) { entry = g_bucket[e * NB + rt0 + t]; g = g_gate[entry]; }
        sEntry[t] = entry; sGate[t] = g;
        sBias[t]  = bias[e * DM + n0 + t];
    }
    if (t == 0) {
#pragma unroll
        for (int s = 0; s < NSTG; s++) {
            mbar_init(smem_u32(&s_full[s]), 256);
            mbar_init(smem_u32(&s_empty[s]), 256);
        }
    }
    __syncthreads();

    uint32_t dynb = smem_u32(sm_dyn);
    uint32_t fullb = smem_u32(&s_full[0]);
    uint32_t emptyb = smem_u32(&s_empty[0]);

    // per-thread cp.async sources: row = t>>1, chunk = t&1 (16B each)
    int lrow = t >> 1, lch = t & 1;
    const __half* a1Src = g_Xh1 + (size_t)(sEntry[lrow] >> 1) * KP + lch * 8;
    const __half* a2Src = g_Xh2 + (size_t)(sEntry[lrow] >> 1) * KP + lch * 8;
    const __half* bSrc  = g_Wh + ((size_t)e * DM + n0 + lrow) * KP + lch * 8;
    uint32_t smoff = swz(lrow, lch);       // swizzled 16B slot for this thread

    // issue one super-stage (2 sub-blocks, 6 cp16 per thread)
    auto issue_super = [&](int sup) {
        uint32_t sb = dynb + (sup % NSTG) * SSTAGE;
#pragma unroll
        for (int s = 0; s < 2; s++) {
            uint32_t ssb = sb + s * SUB;
            int ko = sup * 32 + s * 16;
            cp16(ssb + A1OFF + smoff, a1Src + ko);
            cp16(ssb + A2OFF + smoff, a2Src + ko);
            cp16(ssb + BOFF + smoff, bSrc + ko);
        }
    };

    // prologue: fill supers 0..2; each fill signals its full barrier
    for (int sup = 0; sup < NSTG - 1; sup++) {
        issue_super(sup);
        cp_mbar_arrive_noinc(fullb + (sup & (NSTG - 1)) * 8);
    }

    float acc[4][4][4];
#pragma unroll
    for (int i = 0; i < 4; i++)
#pragma unroll
        for (int j = 0; j < 4; j++)
#pragma unroll
            for (int q = 0; q < 4; q++) acc[i][j][q] = 0.f;

    // fragment address offsets (swizzled; +16-row steps leave swizzle additive)
    int l7 = lane & 7;
    int aRow = wm * 64 + l7 + ((lane >> 3) & 1) * 8;
    uint32_t aRowOff = swz(aRow, (lane >> 4) & 1);
    int bRow = wn * 32 + ((lane >> 4) & 1) * 8 + l7;
    uint32_t bRow4Off = swz(bRow, (lane >> 3) & 1);

    for (int i = 0; i < NSUP; i++) {
        int st = i & (NSTG - 1);
        mbar_wait(fullb + st * 8, (i >> 2) & 1);   // stage i data published

        uint32_t sb = dynb + st * SSTAGE;
#pragma unroll
        for (int s = 0; s < 2; s++) {
            uint32_t ssb = sb + s * SUB;

            // B fragments: 2 ldm_x4 (two tn-pairs)
            uint32_t bh[4][2];
#pragma unroll
            for (int p = 0; p < 2; p++) {
                uint32_t r4[4];
                ldm_x4(r4, ssb + BOFF + bRow4Off + p * 16 * 32);
                bh[2 * p][0] = r4[0]; bh[2 * p][1] = r4[1];
                bh[2 * p + 1][0] = r4[2]; bh[2 * p + 1][1] = r4[3];
            }

            // A fragments (limb1 + limb2): double-buffered across tm
            uint32_t a1[2][4], a2[2][4];
            {
                uint32_t aa = ssb + A1OFF + aRowOff;
                ldm_x4(a1[0], aa);
                ldm_x4(a2[0], aa + (A2OFF - A1OFF));
            }
#pragma unroll
            for (int tm = 0; tm < 4; tm++) {
                int cur = tm & 1;
                if (tm < 3) {
                    uint32_t aa = ssb + A1OFF + aRowOff + (tm + 1) * 16 * 32;
                    ldm_x4(a1[cur ^ 1], aa);
                    ldm_x4(a2[cur ^ 1], aa + (A2OFF - A1OFF));
                }
                // pass-major issue: consecutive MMAs -> independent accumulators
#pragma unroll
                for (int tn = 0; tn < 4; tn++)
                    MMA_F16(acc[tm][tn], a1[cur], bh[tn]);
#pragma unroll
                for (int tn = 0; tn < 4; tn++)
                    MMA_F16(acc[tm][tn], a2[cur], bh[tn]);
            }
        }
        mbar_arrive(emptyb + st * 8);              // done reading stage i

        int sup = i + NSTG - 1;
        if (sup < NSUP) {
            int es = sup & (NSTG - 1);
            if (sup >= NSTG)                        // refill: stage was read before
                mbar_wait(emptyb + es * 8, ((sup - NSTG) >> 2) & 1);
            issue_super(sup);
            cp_mbar_arrive_noinc(fullb + es * 8);
        }
    }

    // epilogue: bias + gate, write to scratch
    int rq = lane >> 2, cq = (lane & 3) * 2;
#pragma unroll
    for (int tm = 0; tm < 4; tm++) {
        int r0 = wm * 64 + tm * 16 + rq;
        int r1 = r0 + 8;
#pragma unroll
        for (int tn = 0; tn < 4; tn++) {
            int cl = wn * 32 + tn * 8 + cq;
            float b0 = sBias[cl], b1 = sBias[cl + 1];
            if (r0 < rows) {
                float g = sGate[r0];
                float2 o = make_float2(g * (acc[tm][tn][0] + b0),
                                       g * (acc[tm][tn][1] + b1));
                *(float2*)(g_scratch + (size_t)sEntry[r0] * DM + n0 + cl) = o;
            }
            if (r1 < rows) {
                float g = sGate[r1];
                float2 o = make_float2(g * (acc[tm][tn][2] + b0),
                                       g * (acc[tm][tn][3] + b1));
                *(float2*)(g_scratch + (size_t)sEntry[r1] * DM + n0 + cl) = o;
            }
        }
    }
}

// ---------------------------------------------------------------------------
// POST: one heterogeneous grid fusing combine + selemb + guide.
__global__ void __launch_bounds__(256) post_kernel(
    const float* __restrict__ selemb,
    float*       __restrict__ out)
{
    int bx = blockIdx.x;
    int t  = threadIdx.x;

    if (bx < POST_CMB) {
        // ---- combine: slot0 + slot1, bf16 quantize, write f32; reset counts
        int idx = bx * 256 + t;
        if (bx == 0 && t < NE) g_count[t] = 0;
        int b  = idx >> 7;
        int m4 = (idx & 127) << 2;
        float g1 = g_gate[2 * b], g2 = g_gate[2 * b + 1];
        float4 v = make_float4(0.f, 0.f, 0.f, 0.f);
        if (g1 > 0.f) {
            float4 s = *(const float4*)(g_scratch + (size_t)(2 * b) * DM + m4);
            v.x += s.x; v.y += s.y; v.z += s.z; v.w += s.w;
        }
        if (g2 > 0.f) {
            float4 s = *(const float4*)(g_scratch + (size_t)(2 * b + 1) * DM + m4);
            v.x += s.x; v.y += s.y; v.z += s.z; v.w += s.w;
        }
        float4 o;
        o.x = __bfloat162float(__float2bfloat16(v.x));
        o.y = __bfloat162float(__float2bfloat16(v.y));
        o.z = __bfloat162float(__float2bfloat16(v.z));
        o.w = __bfloat162float(__float2bfloat16(v.w));
        ((float4*)out)[idx] = o;
    } else if (bx < POST_CMB + POST_SEL) {
        // ---- selemb: out_sel[b,s] = sum_e iw[b,e]*selemb[b,e,s]; warp/token
        int warp = ((bx - POST_CMB) * 256 + t) >> 5;
        int lane = t & 31;
        int b = warp;

        float w[NE];
#pragma unroll
        for (int e = 0; e < NE; e++) w[e] = g_iw[b * NE + e];

        const float4* base = (const float4*)(selemb + (size_t)b * NE * DSEL);
        float4 acc = make_float4(0.f, 0.f, 0.f, 0.f);
#pragma unroll
        for (int e = 0; e < NE; e++) {
            float4 v = base[e * (DSEL / 4) + lane];
            acc.x += w[e] * v.x; acc.y += w[e] * v.y;
            acc.z += w[e] * v.z; acc.w += w[e] * v.w;
        }
        float* dst = out + OUT_SEL + (size_t)b * DSEL + lane * 4;
        dst[0] = acc.x; dst[1] = acc.y; dst[2] = acc.z; dst[3] = acc.w;
    } else {
        // ---- guide: reduce 512 partials
        __shared__ float sm[256];
        sm[t] = g_partial[t] + g_partial[t + 256];
        __syncthreads();
        for (int s = 128; s > 0; s >>= 1) {
            if (t < s) sm[t] += sm[t + s];
            __syncthreads();
        }
        if (t == 0) {
            float sv = sm[0] / (float)NB;
            float d = 1.f - sv;
            out[OUT_GUIDE] = d * d;
        }
    }
}

// ---------------------------------------------------------------------------
extern "C" void kernel_launch(void* const* d_in, const int* in_sizes, int n_in,
                              void* d_out, int out_size)
{
    const float* X      = (const float*)d_in[0];
    const float* logits = (const float*)d_in[1];
    const int*   masks  = (const int*)  d_in[2];
    const float* selemb = (const float*)d_in[3];
    const float* W      = (const float*)d_in[4];
    const float* bias   = (const float*)d_in[5];
    float* out = (float*)d_out;

    cudaFuncSetAttribute(gemm_kernel,
                         cudaFuncAttributeMaxDynamicSharedMemorySize, DYNSM);

    prep_kernel<<<PREP_GRID, 1024>>>(logits, masks, X, W);     // 1
    dim3 g(NB / 128, DM / 128, NE);
    gemm_kernel<<<g, 256, DYNSM>>>(bias);                       // 2
    post_kernel<<<POST_GRID, 256>>>(selemb, out);               // 3
}